// round 5
// baseline (speedup 1.0000x reference)
#include <cuda_runtime.h>
#include <cuda_bf16.h>
#include <cstdint>

#define T_STEPS 10
#define IN_DIM  784
#define HID     256
#define NCLS    47
#define BATCH   4096
#define MROWS   (T_STEPS * BATCH)     /* 40960 */
#define KPAD    832                   /* 784 padded to 13*64 */

// Static device scratch (no cudaMalloc anywhere)
__device__ __nv_bfloat16 g_Bcat[768 * KPAD];   // [W1hi; W1mid; W1lo] K-major
__device__ float g_I[(size_t)MROWS * HID];     // 42MB GEMM output (no bias)
__device__ float g_spkacc[BATCH * HID];        // Sum_t 2^(t-10) spk_t

// ---------------------------------------------------------------------------
// JAX partitionable threefry2x32, key (0,42)
// ---------------------------------------------------------------------------
__device__ __forceinline__ uint32_t rotl32_(uint32_t x, int d) {
    return __funnelshift_l(x, x, d);
}
__device__ __forceinline__ float u01_(uint32_t b) {
    return __uint_as_float((b >> 9) | 0x3f800000u) - 1.0f;
}
__device__ __forceinline__ uint32_t threefry_xor(uint32_t i) {
    uint32_t x0 = 0u, x1 = i;
    const uint32_t ks0 = 0u, ks1 = 42u, ks2 = 42u ^ 0x1BD11BDAu;
    x0 += ks0; x1 += ks1;
#define RND(r) { x0 += x1; x1 = rotl32_(x1, r); x1 ^= x0; }
    RND(13) RND(15) RND(26) RND(6)   x0 += ks1; x1 += ks2 + 1u;
    RND(17) RND(29) RND(16) RND(24)  x0 += ks2; x1 += ks0 + 2u;
    RND(13) RND(15) RND(26) RND(6)   x0 += ks0; x1 += ks1 + 3u;
    RND(17) RND(29) RND(16) RND(24)  x0 += ks1; x1 += ks2 + 4u;
    RND(13) RND(15) RND(26) RND(6)   x0 += ks2; x1 += ks0 + 5u;
#undef RND
    return x0 ^ x1;
}

// ---------------------------------------------------------------------------
// Split W1 (fp32 [784,256]) into exact bf16 triple, K-major, zero-padded.
// ---------------------------------------------------------------------------
__global__ __launch_bounds__(256)
void split_kernel(const float* __restrict__ W1) {
    uint32_t tau = blockIdx.x * 256 + threadIdx.x;   // < 832*256
    uint32_t k = tau % KPAD;
    uint32_t n = tau / KPAD;
    __nv_bfloat16 hi = __float2bfloat16(0.0f), mid = hi, lo = hi;
    if (k < IN_DIM) {
        float w = W1[k * HID + n];
        hi = __float2bfloat16(w);
        float r1 = w - __bfloat162float(hi);                 // exact
        mid = __float2bfloat16(r1);
        lo = __float2bfloat16(r1 - __bfloat162float(mid));   // exact
    }
    g_Bcat[(0 * HID + n) * KPAD + k] = hi;
    g_Bcat[(1 * HID + n) * KPAD + k] = mid;
    g_Bcat[(2 * HID + n) * KPAD + k] = lo;
}

// ---------------------------------------------------------------------------
// Fused RNG + bf16 mma.sync GEMM:
//   I[40960,256] = Bernoulli-spikes(threefry) @ (W1hi+W1mid+W1lo)
// CTA 128x256 (full N), 8 warps (4Mx2N), warp 32x128, K-chunk 64, 2 stages.
// A tile for chunk c+1 is GENERATED (threefry->STS) interleaved with MMAs on
// chunk c; B (3 splits x 256 rows) double-buffered via cp.async.
// ---------------------------------------------------------------------------
#define NCHUNK 13
#define A_ST   16384                    /* 128 rows x 128B */
#define B_SPL  32768                    /* 256 rows x 128B per split */
#define B_ST   (3 * B_SPL)              /* 98304 */
#define SMEM_G (2 * A_ST + 2 * B_ST)    /* 229376 <= 232448 */
#define SWZ(o) ((o) ^ (((o) >> 3) & 0x70))

__device__ __forceinline__ uint32_t s2u(const void* p) {
    uint32_t a;
    asm("{ .reg .u64 t; cvta.to.shared.u64 t, %1; cvt.u32.u64 %0, t; }"
        : "=r"(a) : "l"(p));
    return a;
}
__device__ __forceinline__ void cp16(uint32_t dst, const void* src) {
    asm volatile("cp.async.cg.shared.global [%0], [%1], 16;"
                 :: "r"(dst), "l"(__cvta_generic_to_global(src)));
}
__device__ __forceinline__ void ldsm4(uint32_t& r0, uint32_t& r1,
                                      uint32_t& r2, uint32_t& r3, uint32_t addr) {
    asm volatile("ldmatrix.sync.aligned.m8n8.x4.shared.b16 {%0,%1,%2,%3}, [%4];"
                 : "=r"(r0), "=r"(r1), "=r"(r2), "=r"(r3) : "r"(addr));
}
__device__ __forceinline__ void mma16816(float* c, const uint32_t* a,
                                         uint32_t b0, uint32_t b1) {
    asm volatile("mma.sync.aligned.m16n8k16.row.col.f32.bf16.bf16.f32 "
                 "{%0,%1,%2,%3}, {%4,%5,%6,%7}, {%8,%9}, {%0,%1,%2,%3};"
                 : "+f"(c[0]), "+f"(c[1]), "+f"(c[2]), "+f"(c[3])
                 : "r"(a[0]), "r"(a[1]), "r"(a[2]), "r"(a[3]), "r"(b0), "r"(b1));
}

// Generate 8 spikes (cols j0..j0+7 of row rowg) as bf16 into one 16B smem slot.
__device__ __forceinline__ void genA8(const float* __restrict__ x, int rowg,
                                      int j0, char* dst) {
    uint4 o;
    if (j0 < IN_DIM) {
        uint32_t base = (uint32_t)rowg * IN_DIM + (uint32_t)j0;
        const float* px = x + (size_t)(rowg & (BATCH - 1)) * IN_DIM + j0;
        float4 p0 = *reinterpret_cast<const float4*>(px);
        float4 p1 = *reinterpret_cast<const float4*>(px + 4);
        uint32_t s0 = (u01_(threefry_xor(base + 0)) < p0.x) ? 0x3F80u : 0u;
        uint32_t s1 = (u01_(threefry_xor(base + 1)) < p0.y) ? 0x3F80u : 0u;
        uint32_t s2 = (u01_(threefry_xor(base + 2)) < p0.z) ? 0x3F80u : 0u;
        uint32_t s3 = (u01_(threefry_xor(base + 3)) < p0.w) ? 0x3F80u : 0u;
        uint32_t s4 = (u01_(threefry_xor(base + 4)) < p1.x) ? 0x3F80u : 0u;
        uint32_t s5 = (u01_(threefry_xor(base + 5)) < p1.y) ? 0x3F80u : 0u;
        uint32_t s6 = (u01_(threefry_xor(base + 6)) < p1.z) ? 0x3F80u : 0u;
        uint32_t s7 = (u01_(threefry_xor(base + 7)) < p1.w) ? 0x3F80u : 0u;
        o.x = s0 | (s1 << 16); o.y = s2 | (s3 << 16);
        o.z = s4 | (s5 << 16); o.w = s6 | (s7 << 16);
    } else {
        o = make_uint4(0, 0, 0, 0);
    }
    *reinterpret_cast<uint4*>(dst) = o;
}

__device__ __forceinline__ void cpB(int c, uint32_t bbase, int tid) {
#pragma unroll
    for (int it = 0; it < 24; ++it) {                 // 6144 16B chunks / 256 thr
        int idx = tid + it * 256;
        int s = idx >> 11, rem = idx & 2047;
        int rr = rem >> 3, ch = rem & 7;
        cp16(bbase + s * B_SPL + SWZ(rr * 128 + ch * 16),
             g_Bcat + ((size_t)(s * 256 + rr)) * KPAD + c * 64 + ch * 8);
    }
    asm volatile("cp.async.commit_group;" ::: "memory");
}

__global__ __launch_bounds__(256)
void gemm_kernel(const float* __restrict__ x) {
    extern __shared__ char smem[];
    uint32_t sb = s2u(smem);
    const int tid = threadIdx.x;
    const int wid = tid >> 5, lane = tid & 31;
    const int warp_m = wid & 3, warp_n = wid >> 2;
    const int tile_m = blockIdx.x;

    const int r    = tid >> 1;           // row this thread generates
    const int ch2  = (tid & 1) * 32;     // col half within chunk
    const int rowg = tile_m * 128 + r;

    float acc[2][16][4] = {};

    // Prologue: generate A chunk 0 into stage 0, load B chunk 0 into stage 0.
#pragma unroll
    for (int q = 0; q < 4; ++q) {
        int jl = ch2 + q * 8;
        genA8(x, rowg, jl, smem + SWZ(r * 128 + jl * 2));
    }
    cpB(0, sb + 2 * A_ST, tid);

    const int arow = warp_m * 32 + (lane & 15);
    const int akh  = (lane >> 4) * 8;
    const int nrow = warp_n * 128 + (lane & 7) + ((lane & 16) ? 8 : 0);
    const int bkh  = (lane & 8) ? 8 : 0;

    for (int c = 0; c < NCHUNK; ++c) {
        const int st = c & 1;
        asm volatile("cp.async.wait_group 0;" ::: "memory");
        __syncthreads();

        if (c + 1 < NCHUNK) cpB(c + 1, sb + 2 * A_ST + (st ^ 1) * B_ST, tid);

        uint32_t sA  = sb + st * A_ST;
        uint32_t sBb = sb + 2 * A_ST + st * B_ST;
        char* aDst = smem + (st ^ 1) * A_ST;

#pragma unroll
        for (int ks = 0; ks < 4; ++ks) {
            // interleave next-chunk spike generation with this chunk's MMAs
            if (c + 1 < NCHUNK) {
                int jl = ch2 + ks * 8;
                genA8(x, rowg, (c + 1) * 64 + jl, aDst + SWZ(r * 128 + jl * 2));
            }
            uint32_t a0[4], a1[4];
            ldsm4(a0[0], a0[1], a0[2], a0[3],
                  sA + SWZ(arow * 128 + (ks * 16 + akh) * 2));
            ldsm4(a1[0], a1[1], a1[2], a1[3],
                  sA + SWZ((arow + 16) * 128 + (ks * 16 + akh) * 2));
#pragma unroll
            for (int s = 0; s < 3; ++s) {
                uint32_t sBs = sBb + s * B_SPL;
#pragma unroll
                for (int g = 0; g < 8; ++g) {
                    uint32_t r0, r1, r2, r3;
                    ldsm4(r0, r1, r2, r3,
                          sBs + SWZ((nrow + g * 16) * 128 + (ks * 16 + bkh) * 2));
                    mma16816(acc[0][g * 2 + 0], a0, r0, r1);
                    mma16816(acc[1][g * 2 + 0], a1, r0, r1);
                    mma16816(acc[0][g * 2 + 1], a0, r2, r3);
                    mma16816(acc[1][g * 2 + 1], a1, r2, r3);
                }
            }
        }
        __syncthreads();
    }

    // Epilogue: write fp32 result
    const int rbase = tile_m * 128 + warp_m * 32 + (lane >> 2);
    const int cbase = warp_n * 128 + (lane & 3) * 2;
#pragma unroll
    for (int mf = 0; mf < 2; ++mf) {
#pragma unroll
        for (int nf = 0; nf < 16; ++nf) {
            int rr = rbase + mf * 16;
            int cc = cbase + nf * 8;
            *reinterpret_cast<float2*>(g_I + (size_t)rr * HID + cc) =
                make_float2(acc[mf][nf][0], acc[mf][nf][1]);
            *reinterpret_cast<float2*>(g_I + (size_t)(rr + 8) * HID + cc) =
                make_float2(acc[mf][nf][2], acc[mf][nf][3]);
        }
    }
}

// ---------------------------------------------------------------------------
// LIF recurrence scan: thread per (b,h).
// ---------------------------------------------------------------------------
__global__ __launch_bounds__(256)
void scan_kernel(const float* __restrict__ b1) {
    int tau = blockIdx.x * 256 + threadIdx.x;  // < 4096*256
    int b = tau >> 8, h = tau & 255;
    float bias = b1[h];
    float v = 0.0f, acc = 0.0f;
#pragma unroll
    for (int t = 0; t < T_STEPS; ++t) {
        float I = g_I[((size_t)t * BATCH + b) * HID + h] + bias;
        v = v + (I - v) * 0.5f;
        float spk = ((v - 1.0f) >= 0.0f) ? 1.0f : 0.0f;
        v = v * (1.0f - spk);
        const float ct = (float)(1 << t) * 0x1p-10f;   // 2^(t-10), exact
        acc += ct * spk;
    }
    g_spkacc[tau] = acc;
}

// ---------------------------------------------------------------------------
// Readout: v_out = g_spkacc @ Wr + (1 - 2^-10) * br
// ---------------------------------------------------------------------------
#define BM 64
#define BK 16
#define APAD 4

__global__ __launch_bounds__(256)
void readout_kernel(const float* __restrict__ Wr,
                    const float* __restrict__ br,
                    float* __restrict__ out) {
    __shared__ float As[BK][BM + APAD];
    __shared__ float Bs[BK][48];

    const int tid = threadIdx.x;
    const int bm  = blockIdx.x;
    const int tx  = tid & 15;
    const int ty  = tid >> 4;

    const float* Abase = g_spkacc + (size_t)bm * BM * HID;
    const int arow = tid >> 2;
    const int akq  = (tid & 3) * 4;

    float acc[4][3] = {};

    for (int k0 = 0; k0 < HID; k0 += BK) {
        float4 av = *reinterpret_cast<const float4*>(Abase + (size_t)arow * HID + k0 + akq);
        float bvals[3];
#pragma unroll
        for (int p = 0; p < 3; ++p) {
            int idx = tid + p * 256;
            int kk = idx / 48, cc = idx % 48;
            bvals[p] = (cc < NCLS) ? Wr[(size_t)(k0 + kk) * NCLS + cc] : 0.0f;
        }
        __syncthreads();
        As[akq + 0][arow] = av.x;
        As[akq + 1][arow] = av.y;
        As[akq + 2][arow] = av.z;
        As[akq + 3][arow] = av.w;
#pragma unroll
        for (int p = 0; p < 3; ++p) {
            int idx = tid + p * 256;
            Bs[idx / 48][idx % 48] = bvals[p];
        }
        __syncthreads();
#pragma unroll
        for (int kk = 0; kk < BK; ++kk) {
            float4 a = *reinterpret_cast<const float4*>(&As[kk][ty * 4]);
            float b0  = Bs[kk][tx * 3 + 0];
            float b1v = Bs[kk][tx * 3 + 1];
            float b2  = Bs[kk][tx * 3 + 2];
            acc[0][0] += a.x * b0; acc[0][1] += a.x * b1v; acc[0][2] += a.x * b2;
            acc[1][0] += a.y * b0; acc[1][1] += a.y * b1v; acc[1][2] += a.y * b2;
            acc[2][0] += a.z * b0; acc[2][1] += a.z * b1v; acc[2][2] += a.z * b2;
            acc[3][0] += a.w * b0; acc[3][1] += a.w * b1v; acc[3][2] += a.w * b2;
        }
    }

    const float brc = 1.0f - 0x1p-10f;
    const int grow = bm * BM + ty * 4;
#pragma unroll
    for (int i = 0; i < 4; ++i) {
#pragma unroll
        for (int j = 0; j < 3; ++j) {
            int c = tx * 3 + j;
            if (c < NCLS) {
                out[(size_t)(grow + i) * NCLS + c] = acc[i][j] + brc * br[c];
            }
        }
    }
}

// ---------------------------------------------------------------------------
extern "C" void kernel_launch(void* const* d_in, const int* in_sizes, int n_in,
                              void* d_out, int out_size) {
    const float *x = nullptr, *W1 = nullptr, *b1 = nullptr, *Wr = nullptr, *br = nullptr;
    for (int i = 0; i < n_in; ++i) {
        const float* p = (const float*)d_in[i];
        switch (in_sizes[i]) {
            case BATCH * IN_DIM: x  = p; break;
            case IN_DIM * HID:   W1 = p; break;
            case HID:            b1 = p; break;
            case HID * NCLS:     Wr = p; break;
            case NCLS:           br = p; break;
        }
    }
    float* out = (float*)d_out;

    cudaFuncSetAttribute(gemm_kernel,
                         cudaFuncAttributeMaxDynamicSharedMemorySize, SMEM_G);

    split_kernel<<<(KPAD * HID) / 256, 256>>>(W1);          // 832 blocks
    gemm_kernel<<<MROWS / 128, 256, SMEM_G>>>(x);           // 320 CTAs
    scan_kernel<<<(BATCH * HID) / 256, 256>>>(b1);          // 4096 blocks
    readout_kernel<<<BATCH / BM, 256>>>(Wr, br, out);       // 64 blocks
}

// round 6
// speedup vs baseline: 1.2499x; 1.2499x over previous
#include <cuda_runtime.h>
#include <cuda_bf16.h>
#include <cstdint>

#define T_STEPS 10
#define IN_DIM  784
#define HID     256
#define NCLS    47
#define BATCH   4096
#define MROWS   (T_STEPS * BATCH)     /* 40960 */
#define KPAD    832                   /* 784 padded to 13*64 */

// Static device scratch (no cudaMalloc anywhere)
__device__ __nv_bfloat16 g_Bcat[768 * KPAD];   // [W1hi; W1mid; W1lo] K-major
__device__ float g_I[(size_t)MROWS * HID];     // 42MB GEMM output (no bias)
__device__ float g_spkacc[BATCH * HID];        // Sum_t 2^(t-10) spk_t

// ---------------------------------------------------------------------------
// JAX partitionable threefry2x32, key (0,42)
// ---------------------------------------------------------------------------
__device__ __forceinline__ uint32_t rotl32_(uint32_t x, int d) {
    return __funnelshift_l(x, x, d);
}
__device__ __forceinline__ float u01_(uint32_t b) {
    return __uint_as_float((b >> 9) | 0x3f800000u) - 1.0f;
}
__device__ __forceinline__ uint32_t threefry_xor(uint32_t i) {
    uint32_t x0 = 0u, x1 = i;
    const uint32_t ks0 = 0u, ks1 = 42u, ks2 = 42u ^ 0x1BD11BDAu;
    x0 += ks0; x1 += ks1;
#define RND(r) { x0 += x1; x1 = rotl32_(x1, r); x1 ^= x0; }
    RND(13) RND(15) RND(26) RND(6)   x0 += ks1; x1 += ks2 + 1u;
    RND(17) RND(29) RND(16) RND(24)  x0 += ks2; x1 += ks0 + 2u;
    RND(13) RND(15) RND(26) RND(6)   x0 += ks0; x1 += ks1 + 3u;
    RND(17) RND(29) RND(16) RND(24)  x0 += ks1; x1 += ks2 + 4u;
    RND(13) RND(15) RND(26) RND(6)   x0 += ks2; x1 += ks0 + 5u;
#undef RND
    return x0 ^ x1;
}

// ---------------------------------------------------------------------------
// Split W1 (fp32 [784,256]) into exact bf16 triple, K-major, zero-padded.
// ---------------------------------------------------------------------------
__global__ __launch_bounds__(256)
void split_kernel(const float* __restrict__ W1) {
    uint32_t tau = blockIdx.x * 256 + threadIdx.x;   // < 832*256
    uint32_t k = tau % KPAD;
    uint32_t n = tau / KPAD;
    __nv_bfloat16 hi = __float2bfloat16(0.0f), mid = hi, lo = hi;
    if (k < IN_DIM) {
        float w = W1[k * HID + n];
        hi = __float2bfloat16(w);
        float r1 = w - __bfloat162float(hi);                 // exact
        mid = __float2bfloat16(r1);
        lo = __float2bfloat16(r1 - __bfloat162float(mid));   // exact
    }
    g_Bcat[(0 * HID + n) * KPAD + k] = hi;
    g_Bcat[(1 * HID + n) * KPAD + k] = mid;
    g_Bcat[(2 * HID + n) * KPAD + k] = lo;
}

// ---------------------------------------------------------------------------
// Fused warp-specialized RNG + bf16 mma.sync GEMM:
//   I[40960,256] = Bernoulli-spikes(threefry) @ (W1hi+W1mid+W1lo)
// CTA tile 64x256 (full N -> each hash computed exactly once).
// 16 warps: warps 0-7 = MMA consumers (warp 32x64, 64 acc regs),
//           warps 8-15 = producers (threefry->STS A, cp.async B), 2 stages.
// ---------------------------------------------------------------------------
#define NCHUNK 13
#define A_ST   8192                     /* 64 rows x 128B */
#define B_SPL  32768                    /* 256 rows x 128B per split */
#define B_ST   (3 * B_SPL)              /* 98304 */
#define B_BASE (2 * A_ST)               /* 16384 */
#define SMEM_G (B_BASE + 2 * B_ST)      /* 212992 <= 232448 */
#define SWZ(o) ((o) ^ (((o) >> 3) & 0x70))

__device__ __forceinline__ uint32_t s2u(const void* p) {
    uint32_t a;
    asm("{ .reg .u64 t; cvta.to.shared.u64 t, %1; cvt.u32.u64 %0, t; }"
        : "=r"(a) : "l"(p));
    return a;
}
__device__ __forceinline__ void cp16(uint32_t dst, const void* src) {
    asm volatile("cp.async.cg.shared.global [%0], [%1], 16;"
                 :: "r"(dst), "l"(__cvta_generic_to_global(src)));
}
__device__ __forceinline__ void ldsm4(uint32_t& r0, uint32_t& r1,
                                      uint32_t& r2, uint32_t& r3, uint32_t addr) {
    asm volatile("ldmatrix.sync.aligned.m8n8.x4.shared.b16 {%0,%1,%2,%3}, [%4];"
                 : "=r"(r0), "=r"(r1), "=r"(r2), "=r"(r3) : "r"(addr));
}
__device__ __forceinline__ void mma16816(float* c, const uint32_t* a,
                                         uint32_t b0, uint32_t b1) {
    asm volatile("mma.sync.aligned.m16n8k16.row.col.f32.bf16.bf16.f32 "
                 "{%0,%1,%2,%3}, {%4,%5,%6,%7}, {%8,%9}, {%0,%1,%2,%3};"
                 : "+f"(c[0]), "+f"(c[1]), "+f"(c[2]), "+f"(c[3])
                 : "r"(a[0]), "r"(a[1]), "r"(a[2]), "r"(a[3]), "r"(b0), "r"(b1));
}

// Generate 8 spikes (cols j0..j0+7 of row rowg) as bf16 into one 16B smem slot.
__device__ __forceinline__ void genA8(const float* __restrict__ x, int rowg,
                                      int j0, char* dst) {
    uint4 o;
    if (j0 < IN_DIM) {
        uint32_t base = (uint32_t)rowg * IN_DIM + (uint32_t)j0;
        const float* px = x + (size_t)(rowg & (BATCH - 1)) * IN_DIM + j0;
        float4 p0 = *reinterpret_cast<const float4*>(px);
        float4 p1 = *reinterpret_cast<const float4*>(px + 4);
        uint32_t s0 = (u01_(threefry_xor(base + 0)) < p0.x) ? 0x3F80u : 0u;
        uint32_t s1 = (u01_(threefry_xor(base + 1)) < p0.y) ? 0x3F80u : 0u;
        uint32_t s2 = (u01_(threefry_xor(base + 2)) < p0.z) ? 0x3F80u : 0u;
        uint32_t s3 = (u01_(threefry_xor(base + 3)) < p0.w) ? 0x3F80u : 0u;
        uint32_t s4 = (u01_(threefry_xor(base + 4)) < p1.x) ? 0x3F80u : 0u;
        uint32_t s5 = (u01_(threefry_xor(base + 5)) < p1.y) ? 0x3F80u : 0u;
        uint32_t s6 = (u01_(threefry_xor(base + 6)) < p1.z) ? 0x3F80u : 0u;
        uint32_t s7 = (u01_(threefry_xor(base + 7)) < p1.w) ? 0x3F80u : 0u;
        o.x = s0 | (s1 << 16); o.y = s2 | (s3 << 16);
        o.z = s4 | (s5 << 16); o.w = s6 | (s7 << 16);
    } else {
        o = make_uint4(0, 0, 0, 0);
    }
    *reinterpret_cast<uint4*>(dst) = o;
}

// Producers (256 threads) stage one B chunk: 3 splits x 256 rows x 128B.
__device__ __forceinline__ void cpB(int c, uint32_t bbase, int ptid) {
#pragma unroll
    for (int it = 0; it < 24; ++it) {                 // 6144 16B chunks / 256 thr
        int idx = ptid + it * 256;
        int s = idx >> 11, rem = idx & 2047;
        int rr = rem >> 3, ch = rem & 7;
        cp16(bbase + s * B_SPL + SWZ(rr * 128 + ch * 16),
             g_Bcat + (size_t)(s * 256 + rr) * KPAD + c * 64 + ch * 8);
    }
    asm volatile("cp.async.commit_group;" ::: "memory");
}

__global__ __launch_bounds__(512)
void gemm_kernel(const float* __restrict__ x) {
    extern __shared__ char smem[];
    uint32_t sb = s2u(smem);
    const int tid = threadIdx.x;
    const int wid = tid >> 5, lane = tid & 31;
    const int tile_m = blockIdx.x;                    // 0..639
    const bool producer = (wid >= 8);

    // producer-only state
    const int ptid = tid - 256;                       // 0..255 (garbage for cons.)
    const int pr   = (ptid & 255) >> 2;               // row 0..63
    const int pc   = (ptid & 3) * 16;                 // col group (16 cols)
    const int rowg = tile_m * 64 + pr;

    // consumer-only state
    const int warp_m = wid & 1, warp_n = wid >> 1;
    const int arow = warp_m * 32 + (lane & 15);
    const int akh  = (lane >> 4) * 8;
    const int nrow = warp_n * 64 + (lane & 7) + ((lane & 16) ? 8 : 0);
    const int bkh  = (lane & 8) ? 8 : 0;
    float acc[2][8][4] = {};

    // Prologue: producers fill stage 0 (A chunk 0 + B chunk 0).
    if (producer) {
        genA8(x, rowg, pc,     smem + SWZ(pr * 128 + pc * 2));
        genA8(x, rowg, pc + 8, smem + SWZ(pr * 128 + (pc + 8) * 2));
        cpB(0, sb + B_BASE, ptid);
        asm volatile("cp.async.wait_group 0;" ::: "memory");
    }
    __syncthreads();

    for (int c = 0; c < NCHUNK; ++c) {
        const int st = c & 1;
        if (producer) {
            if (c + 1 < NCHUNK) {
                char* aDst = smem + (st ^ 1) * A_ST;
                int j0 = (c + 1) * 64 + pc;
                genA8(x, rowg, j0,     aDst + SWZ(pr * 128 + pc * 2));
                genA8(x, rowg, j0 + 8, aDst + SWZ(pr * 128 + (pc + 8) * 2));
                cpB(c + 1, sb + B_BASE + (st ^ 1) * B_ST, ptid);
                asm volatile("cp.async.wait_group 0;" ::: "memory");
            }
        } else {
            uint32_t sA  = sb + st * A_ST;
            uint32_t sBb = sb + B_BASE + st * B_ST;
#pragma unroll
            for (int ks = 0; ks < 4; ++ks) {
                uint32_t a0[4], a1[4];
                ldsm4(a0[0], a0[1], a0[2], a0[3],
                      sA + SWZ(arow * 128 + (ks * 16 + akh) * 2));
                ldsm4(a1[0], a1[1], a1[2], a1[3],
                      sA + SWZ((arow + 16) * 128 + (ks * 16 + akh) * 2));
#pragma unroll
                for (int s = 0; s < 3; ++s) {
                    uint32_t sBs = sBb + s * B_SPL;
#pragma unroll
                    for (int g = 0; g < 4; ++g) {
                        uint32_t r0, r1, r2, r3;
                        ldsm4(r0, r1, r2, r3,
                              sBs + SWZ((nrow + g * 16) * 128 + (ks * 16 + bkh) * 2));
                        mma16816(acc[0][g * 2 + 0], a0, r0, r1);
                        mma16816(acc[1][g * 2 + 0], a1, r0, r1);
                        mma16816(acc[0][g * 2 + 1], a0, r2, r3);
                        mma16816(acc[1][g * 2 + 1], a1, r2, r3);
                    }
                }
            }
        }
        __syncthreads();
    }

    // Epilogue: consumers write fp32 result
    if (!producer) {
        const int rbase = tile_m * 64 + warp_m * 32 + (lane >> 2);
        const int cbase = warp_n * 64 + (lane & 3) * 2;
#pragma unroll
        for (int mf = 0; mf < 2; ++mf) {
#pragma unroll
            for (int nf = 0; nf < 8; ++nf) {
                int rr = rbase + mf * 16;
                int cc = cbase + nf * 8;
                *reinterpret_cast<float2*>(g_I + (size_t)rr * HID + cc) =
                    make_float2(acc[mf][nf][0], acc[mf][nf][1]);
                *reinterpret_cast<float2*>(g_I + (size_t)(rr + 8) * HID + cc) =
                    make_float2(acc[mf][nf][2], acc[mf][nf][3]);
            }
        }
    }
}

// ---------------------------------------------------------------------------
// LIF recurrence scan: thread per (b, 4 channels), float4 traffic.
// ---------------------------------------------------------------------------
__global__ __launch_bounds__(256)
void scan_kernel(const float* __restrict__ b1) {
    int tau = blockIdx.x * 256 + threadIdx.x;  // < 4096*64
    int b = tau >> 6, h4 = (tau & 63) * 4;
    float4 bias = *reinterpret_cast<const float4*>(b1 + h4);
    float4 v = make_float4(0.f, 0.f, 0.f, 0.f);
    float4 acc = make_float4(0.f, 0.f, 0.f, 0.f);
#pragma unroll
    for (int t = 0; t < T_STEPS; ++t) {
        float4 I = *reinterpret_cast<const float4*>(
            g_I + ((size_t)t * BATCH + b) * HID + h4);
        const float ct = (float)(1 << t) * 0x1p-10f;   // 2^(t-10), exact
#define LIF(comp) { \
        float Ii = I.comp + bias.comp; \
        v.comp = v.comp + (Ii - v.comp) * 0.5f; \
        float spk = ((v.comp - 1.0f) >= 0.0f) ? 1.0f : 0.0f; \
        v.comp = v.comp * (1.0f - spk); \
        acc.comp += ct * spk; }
        LIF(x) LIF(y) LIF(z) LIF(w)
#undef LIF
    }
    *reinterpret_cast<float4*>(g_spkacc + (size_t)b * HID + h4) = acc;
}

// ---------------------------------------------------------------------------
// Readout: v_out = g_spkacc @ Wr + (1 - 2^-10) * br
// BM=32, 128 threads, grid 128 (2x parallelism vs R4).
// ---------------------------------------------------------------------------
#define BM 32
#define BK 16
#define APAD 4

__global__ __launch_bounds__(128)
void readout_kernel(const float* __restrict__ Wr,
                    const float* __restrict__ br,
                    float* __restrict__ out) {
    __shared__ float As[BK][BM + APAD];
    __shared__ float Bs[BK][48];

    const int tid = threadIdx.x;
    const int bm  = blockIdx.x;
    const int tx  = tid & 15;            // 3 cols each
    const int ty  = tid >> 4;            // 0..7 -> 4 rows each

    const float* Abase = g_spkacc + (size_t)bm * BM * HID;
    const int arow = tid >> 2;           // 0..31
    const int akq  = (tid & 3) * 4;

    float acc[4][3] = {};

    for (int k0 = 0; k0 < HID; k0 += BK) {
        float4 av = *reinterpret_cast<const float4*>(Abase + (size_t)arow * HID + k0 + akq);
        float bvals[6];
#pragma unroll
        for (int p = 0; p < 6; ++p) {
            int idx = tid + p * 128;              // < 768 = 16*48
            int kk = idx / 48, cc = idx % 48;
            bvals[p] = (cc < NCLS) ? Wr[(size_t)(k0 + kk) * NCLS + cc] : 0.0f;
        }
        __syncthreads();
        As[akq + 0][arow] = av.x;
        As[akq + 1][arow] = av.y;
        As[akq + 2][arow] = av.z;
        As[akq + 3][arow] = av.w;
#pragma unroll
        for (int p = 0; p < 6; ++p) {
            int idx = tid + p * 128;
            Bs[idx / 48][idx % 48] = bvals[p];
        }
        __syncthreads();
#pragma unroll
        for (int kk = 0; kk < BK; ++kk) {
            float4 a = *reinterpret_cast<const float4*>(&As[kk][ty * 4]);
            float b0  = Bs[kk][tx * 3 + 0];
            float b1v = Bs[kk][tx * 3 + 1];
            float b2  = Bs[kk][tx * 3 + 2];
            acc[0][0] += a.x * b0; acc[0][1] += a.x * b1v; acc[0][2] += a.x * b2;
            acc[1][0] += a.y * b0; acc[1][1] += a.y * b1v; acc[1][2] += a.y * b2;
            acc[2][0] += a.z * b0; acc[2][1] += a.z * b1v; acc[2][2] += a.z * b2;
            acc[3][0] += a.w * b0; acc[3][1] += a.w * b1v; acc[3][2] += a.w * b2;
        }
    }

    const float brc = 1.0f - 0x1p-10f;
    const int grow = bm * BM + ty * 4;
#pragma unroll
    for (int i = 0; i < 4; ++i) {
#pragma unroll
        for (int j = 0; j < 3; ++j) {
            int c = tx * 3 + j;
            if (c < NCLS) {
                out[(size_t)(grow + i) * NCLS + c] = acc[i][j] + brc * br[c];
            }
        }
    }
}

// ---------------------------------------------------------------------------
extern "C" void kernel_launch(void* const* d_in, const int* in_sizes, int n_in,
                              void* d_out, int out_size) {
    const float *x = nullptr, *W1 = nullptr, *b1 = nullptr, *Wr = nullptr, *br = nullptr;
    for (int i = 0; i < n_in; ++i) {
        const float* p = (const float*)d_in[i];
        switch (in_sizes[i]) {
            case BATCH * IN_DIM: x  = p; break;
            case IN_DIM * HID:   W1 = p; break;
            case HID:            b1 = p; break;
            case HID * NCLS:     Wr = p; break;
            case NCLS:           br = p; break;
        }
    }
    float* out = (float*)d_out;

    cudaFuncSetAttribute(gemm_kernel,
                         cudaFuncAttributeMaxDynamicSharedMemorySize, SMEM_G);

    split_kernel<<<(KPAD * HID) / 256, 256>>>(W1);          // 832 blocks
    gemm_kernel<<<MROWS / 64, 512, SMEM_G>>>(x);            // 640 CTAs
    scan_kernel<<<(BATCH * 64) / 256, 256>>>(b1);           // 1024 blocks
    readout_kernel<<<BATCH / BM, 128>>>(Wr, br, out);       // 128 blocks
}

// round 7
// speedup vs baseline: 1.3341x; 1.0674x over previous
#include <cuda_runtime.h>
#include <cuda_bf16.h>
#include <cstdint>

#define T_STEPS 10
#define IN_DIM  784
#define HID     256
#define NCLS    47
#define BATCH   4096
#define MROWS   (T_STEPS * BATCH)     /* 40960 */
#define KPAD    832                   /* 784 padded to 13*64 */

// Static device scratch (no cudaMalloc anywhere)
__device__ __nv_bfloat16 g_Bcat[768 * KPAD];   // [W1hi; W1mid; W1lo] K-major
__device__ float g_I[(size_t)MROWS * HID];     // 42MB GEMM output (no bias)

// ---------------------------------------------------------------------------
// JAX partitionable threefry2x32, key (0,42)
// ---------------------------------------------------------------------------
__device__ __forceinline__ uint32_t rotl32_(uint32_t x, int d) {
    return __funnelshift_l(x, x, d);
}
__device__ __forceinline__ float u01_(uint32_t b) {
    return __uint_as_float((b >> 9) | 0x3f800000u) - 1.0f;
}
__device__ __forceinline__ uint32_t threefry_xor(uint32_t i) {
    uint32_t x0 = 0u, x1 = i;
    const uint32_t ks0 = 0u, ks1 = 42u, ks2 = 42u ^ 0x1BD11BDAu;
    x0 += ks0; x1 += ks1;
#define RND(r) { x0 += x1; x1 = rotl32_(x1, r); x1 ^= x0; }
    RND(13) RND(15) RND(26) RND(6)   x0 += ks1; x1 += ks2 + 1u;
    RND(17) RND(29) RND(16) RND(24)  x0 += ks2; x1 += ks0 + 2u;
    RND(13) RND(15) RND(26) RND(6)   x0 += ks0; x1 += ks1 + 3u;
    RND(17) RND(29) RND(16) RND(24)  x0 += ks1; x1 += ks2 + 4u;
    RND(13) RND(15) RND(26) RND(6)   x0 += ks2; x1 += ks0 + 5u;
#undef RND
    return x0 ^ x1;
}

// ---------------------------------------------------------------------------
// Split W1 (fp32 [784,256]) into exact bf16 triple, K-major, zero-padded.
// ---------------------------------------------------------------------------
__global__ __launch_bounds__(256)
void split_kernel(const float* __restrict__ W1) {
    uint32_t tau = blockIdx.x * 256 + threadIdx.x;   // < 832*256
    uint32_t k = tau % KPAD;
    uint32_t n = tau / KPAD;
    __nv_bfloat16 hi = __float2bfloat16(0.0f), mid = hi, lo = hi;
    if (k < IN_DIM) {
        float w = W1[k * HID + n];
        hi = __float2bfloat16(w);
        float r1 = w - __bfloat162float(hi);                 // exact
        mid = __float2bfloat16(r1);
        lo = __float2bfloat16(r1 - __bfloat162float(mid));   // exact
    }
    g_Bcat[(0 * HID + n) * KPAD + k] = hi;
    g_Bcat[(1 * HID + n) * KPAD + k] = mid;
    g_Bcat[(2 * HID + n) * KPAD + k] = lo;
}

// ---------------------------------------------------------------------------
// Fused warp-specialized RNG + bf16 mma.sync GEMM:
//   I[40960,256] = Bernoulli-spikes(threefry) @ (W1hi+W1mid+W1lo)
// CTA tile 64x256 (full N -> each hash computed exactly once).
// 16 warps: warps 0-7 = MMA consumers (warp 32x64, 64 acc regs),
//           warps 8-15 = producers: cp.async B FIRST (L2 service hides under
//           the threefry issue burst), then threefry->STS A, then wait.
// ---------------------------------------------------------------------------
#define NCHUNK 13
#define A_ST   8192                     /* 64 rows x 128B */
#define B_SPL  32768                    /* 256 rows x 128B per split */
#define B_ST   (3 * B_SPL)              /* 98304 */
#define B_BASE (2 * A_ST)               /* 16384 */
#define SMEM_G (B_BASE + 2 * B_ST)      /* 212992 <= 232448 */
#define SWZ(o) ((o) ^ (((o) >> 3) & 0x70))

__device__ __forceinline__ uint32_t s2u(const void* p) {
    uint32_t a;
    asm("{ .reg .u64 t; cvta.to.shared.u64 t, %1; cvt.u32.u64 %0, t; }"
        : "=r"(a) : "l"(p));
    return a;
}
__device__ __forceinline__ void cp16(uint32_t dst, const void* src) {
    asm volatile("cp.async.cg.shared.global [%0], [%1], 16;"
                 :: "r"(dst), "l"(__cvta_generic_to_global(src)));
}
__device__ __forceinline__ void ldsm4(uint32_t& r0, uint32_t& r1,
                                      uint32_t& r2, uint32_t& r3, uint32_t addr) {
    asm volatile("ldmatrix.sync.aligned.m8n8.x4.shared.b16 {%0,%1,%2,%3}, [%4];"
                 : "=r"(r0), "=r"(r1), "=r"(r2), "=r"(r3) : "r"(addr));
}
__device__ __forceinline__ void mma16816(float* c, const uint32_t* a,
                                         uint32_t b0, uint32_t b1) {
    asm volatile("mma.sync.aligned.m16n8k16.row.col.f32.bf16.bf16.f32 "
                 "{%0,%1,%2,%3}, {%4,%5,%6,%7}, {%8,%9}, {%0,%1,%2,%3};"
                 : "+f"(c[0]), "+f"(c[1]), "+f"(c[2]), "+f"(c[3])
                 : "r"(a[0]), "r"(a[1]), "r"(a[2]), "r"(a[3]), "r"(b0), "r"(b1));
}

// Generate 8 spikes (cols j0..j0+7 of row rowg) as bf16 into one 16B smem slot.
__device__ __forceinline__ void genA8(const float* __restrict__ x, int rowg,
                                      int j0, char* dst) {
    uint4 o;
    if (j0 < IN_DIM) {
        uint32_t base = (uint32_t)rowg * IN_DIM + (uint32_t)j0;
        const float* px = x + (size_t)(rowg & (BATCH - 1)) * IN_DIM + j0;
        float4 p0 = *reinterpret_cast<const float4*>(px);
        float4 p1 = *reinterpret_cast<const float4*>(px + 4);
        uint32_t s0 = (u01_(threefry_xor(base + 0)) < p0.x) ? 0x3F80u : 0u;
        uint32_t s1 = (u01_(threefry_xor(base + 1)) < p0.y) ? 0x3F80u : 0u;
        uint32_t s2 = (u01_(threefry_xor(base + 2)) < p0.z) ? 0x3F80u : 0u;
        uint32_t s3 = (u01_(threefry_xor(base + 3)) < p0.w) ? 0x3F80u : 0u;
        uint32_t s4 = (u01_(threefry_xor(base + 4)) < p1.x) ? 0x3F80u : 0u;
        uint32_t s5 = (u01_(threefry_xor(base + 5)) < p1.y) ? 0x3F80u : 0u;
        uint32_t s6 = (u01_(threefry_xor(base + 6)) < p1.z) ? 0x3F80u : 0u;
        uint32_t s7 = (u01_(threefry_xor(base + 7)) < p1.w) ? 0x3F80u : 0u;
        o.x = s0 | (s1 << 16); o.y = s2 | (s3 << 16);
        o.z = s4 | (s5 << 16); o.w = s6 | (s7 << 16);
    } else {
        o = make_uint4(0, 0, 0, 0);
    }
    *reinterpret_cast<uint4*>(dst) = o;
}

// Producers (256 threads) stage one B chunk: 3 splits x 256 rows x 128B.
__device__ __forceinline__ void cpB(int c, uint32_t bbase, int ptid) {
#pragma unroll
    for (int it = 0; it < 24; ++it) {                 // 6144 16B chunks / 256 thr
        int idx = ptid + it * 256;
        int s = idx >> 11, rem = idx & 2047;
        int rr = rem >> 3, ch = rem & 7;
        cp16(bbase + s * B_SPL + SWZ(rr * 128 + ch * 16),
             g_Bcat + (size_t)(s * 256 + rr) * KPAD + c * 64 + ch * 8);
    }
    asm volatile("cp.async.commit_group;" ::: "memory");
}

__global__ __launch_bounds__(512)
void gemm_kernel(const float* __restrict__ x) {
    extern __shared__ char smem[];
    uint32_t sb = s2u(smem);
    const int tid = threadIdx.x;
    const int wid = tid >> 5, lane = tid & 31;
    const int tile_m = blockIdx.x;                    // 0..639
    const bool producer = (wid >= 8);

    // producer-only state
    const int ptid = tid - 256;                       // 0..255 (garbage for cons.)
    const int pr   = (ptid & 255) >> 2;               // row 0..63
    const int pc   = (ptid & 3) * 16;                 // col group (16 cols)
    const int rowg = tile_m * 64 + pr;

    // consumer-only state
    const int warp_m = wid & 1, warp_n = wid >> 1;
    const int arow = warp_m * 32 + (lane & 15);
    const int akh  = (lane >> 4) * 8;
    const int nrow = warp_n * 64 + (lane & 7) + ((lane & 16) ? 8 : 0);
    const int bkh  = (lane & 8) ? 8 : 0;
    float acc[2][8][4] = {};

    // Prologue: producers fill stage 0. B load issued FIRST so its L2 service
    // overlaps the threefry issue burst.
    if (producer) {
        cpB(0, sb + B_BASE, ptid);
        genA8(x, rowg, pc,     smem + SWZ(pr * 128 + pc * 2));
        genA8(x, rowg, pc + 8, smem + SWZ(pr * 128 + (pc + 8) * 2));
        asm volatile("cp.async.wait_group 0;" ::: "memory");
    }
    __syncthreads();

    for (int c = 0; c < NCHUNK; ++c) {
        const int st = c & 1;
        if (producer) {
            if (c + 1 < NCHUNK) {
                cpB(c + 1, sb + B_BASE + (st ^ 1) * B_ST, ptid);   // B first
                char* aDst = smem + (st ^ 1) * A_ST;
                int j0 = (c + 1) * 64 + pc;
                genA8(x, rowg, j0,     aDst + SWZ(pr * 128 + pc * 2));
                genA8(x, rowg, j0 + 8, aDst + SWZ(pr * 128 + (pc + 8) * 2));
                asm volatile("cp.async.wait_group 0;" ::: "memory");
            }
        } else {
            uint32_t sA  = sb + st * A_ST;
            uint32_t sBb = sb + B_BASE + st * B_ST;
#pragma unroll
            for (int ks = 0; ks < 4; ++ks) {
                uint32_t a0[4], a1[4];
                ldsm4(a0[0], a0[1], a0[2], a0[3],
                      sA + SWZ(arow * 128 + (ks * 16 + akh) * 2));
                ldsm4(a1[0], a1[1], a1[2], a1[3],
                      sA + SWZ((arow + 16) * 128 + (ks * 16 + akh) * 2));
#pragma unroll
                for (int s = 0; s < 3; ++s) {
                    uint32_t sBs = sBb + s * B_SPL;
#pragma unroll
                    for (int g = 0; g < 4; ++g) {
                        uint32_t r0, r1, r2, r3;
                        ldsm4(r0, r1, r2, r3,
                              sBs + SWZ((nrow + g * 16) * 128 + (ks * 16 + bkh) * 2));
                        mma16816(acc[0][g * 2 + 0], a0, r0, r1);
                        mma16816(acc[1][g * 2 + 0], a1, r0, r1);
                        mma16816(acc[0][g * 2 + 1], a0, r2, r3);
                        mma16816(acc[1][g * 2 + 1], a1, r2, r3);
                    }
                }
            }
        }
        __syncthreads();
    }

    // Epilogue: consumers write fp32 result
    if (!producer) {
        const int rbase = tile_m * 64 + warp_m * 32 + (lane >> 2);
        const int cbase = warp_n * 64 + (lane & 3) * 2;
#pragma unroll
        for (int mf = 0; mf < 2; ++mf) {
#pragma unroll
            for (int nf = 0; nf < 8; ++nf) {
                int rr = rbase + mf * 16;
                int cc = cbase + nf * 8;
                *reinterpret_cast<float2*>(g_I + (size_t)rr * HID + cc) =
                    make_float2(acc[mf][nf][0], acc[mf][nf][1]);
                *reinterpret_cast<float2*>(g_I + (size_t)(rr + 8) * HID + cc) =
                    make_float2(acc[mf][nf][2], acc[mf][nf][3]);
            }
        }
    }
}

// ---------------------------------------------------------------------------
// Fused LIF scan + readout: one block per batch row b.
//   64 threads: LIF over t for 4 channels each -> smem acc[256];
//   then threads 0..46 compute out[b][c] = acc . Wr[:,c] + (1-2^-10) br[c].
// ---------------------------------------------------------------------------
__global__ __launch_bounds__(64)
void scan_readout_kernel(const float* __restrict__ b1,
                         const float* __restrict__ Wr,
                         const float* __restrict__ br,
                         float* __restrict__ out) {
    __shared__ float sacc[HID];
    const int b = blockIdx.x;
    const int tid = threadIdx.x;         // 0..63
    const int h4 = tid * 4;

    float4 bias = *reinterpret_cast<const float4*>(b1 + h4);
    float4 v   = make_float4(0.f, 0.f, 0.f, 0.f);
    float4 acc = make_float4(0.f, 0.f, 0.f, 0.f);
#pragma unroll
    for (int t = 0; t < T_STEPS; ++t) {
        float4 I = *reinterpret_cast<const float4*>(
            g_I + ((size_t)t * BATCH + b) * HID + h4);
        const float ct = (float)(1 << t) * 0x1p-10f;   // 2^(t-10), exact
#define LIF(comp) { \
        float Ii = I.comp + bias.comp; \
        v.comp = v.comp + (Ii - v.comp) * 0.5f; \
        float spk = ((v.comp - 1.0f) >= 0.0f) ? 1.0f : 0.0f; \
        v.comp = v.comp * (1.0f - spk); \
        acc.comp += ct * spk; }
        LIF(x) LIF(y) LIF(z) LIF(w)
#undef LIF
    }
    *reinterpret_cast<float4*>(sacc + h4) = acc;
    __syncthreads();

    if (tid < NCLS) {
        float s0 = (1.0f - 0x1p-10f) * br[tid];
        float s1 = 0.f, s2 = 0.f, s3 = 0.f;
#pragma unroll 4
        for (int h = 0; h < HID; h += 4) {
            s0 += sacc[h + 0] * Wr[(h + 0) * NCLS + tid];
            s1 += sacc[h + 1] * Wr[(h + 1) * NCLS + tid];
            s2 += sacc[h + 2] * Wr[(h + 2) * NCLS + tid];
            s3 += sacc[h + 3] * Wr[(h + 3) * NCLS + tid];
        }
        out[(size_t)b * NCLS + tid] = ((s0 + s1) + (s2 + s3));
    }
}

// ---------------------------------------------------------------------------
extern "C" void kernel_launch(void* const* d_in, const int* in_sizes, int n_in,
                              void* d_out, int out_size) {
    const float *x = nullptr, *W1 = nullptr, *b1 = nullptr, *Wr = nullptr, *br = nullptr;
    for (int i = 0; i < n_in; ++i) {
        const float* p = (const float*)d_in[i];
        switch (in_sizes[i]) {
            case BATCH * IN_DIM: x  = p; break;
            case IN_DIM * HID:   W1 = p; break;
            case HID:            b1 = p; break;
            case HID * NCLS:     Wr = p; break;
            case NCLS:           br = p; break;
        }
    }
    float* out = (float*)d_out;

    cudaFuncSetAttribute(gemm_kernel,
                         cudaFuncAttributeMaxDynamicSharedMemorySize, SMEM_G);

    split_kernel<<<(KPAD * HID) / 256, 256>>>(W1);          // 832 blocks
    gemm_kernel<<<MROWS / 64, 512, SMEM_G>>>(x);            // 640 CTAs
    scan_readout_kernel<<<BATCH, 64>>>(b1, Wr, br, out);    // 4096 blocks
}